// round 6
// baseline (speedup 1.0000x reference)
#include <cuda_runtime.h>
#include <cstdint>

// Problem constants
constexpr int kNB = 2;
constexpr int kNT = 2048;
constexpr int kND = 1024;
constexpr int kNH = 16;
constexpr int kNM = kNB * kNT;   // 4096 rows

// Scratch (allocation-free rule: device globals)
__device__ float g_qkv[(size_t)kNM * 3 * kND];    // (4096, 3072)
__device__ float g_attn[(size_t)kNM * kND];       // (4096, 1024) tf32-rounded
__device__ float g_xc[(size_t)kNM * kND];         // x, tf32-rounded
__device__ float g_wac[(size_t)kND * 3 * kND];    // W_attn rounded, [k][n]
__device__ float g_wpc[(size_t)kND * kND];        // W_proj rounded, [k][n]

// ---------------------------------------------------------------------------
// Helpers
// ---------------------------------------------------------------------------
__device__ __forceinline__ unsigned f2tf32(float f) {
    unsigned u;
    asm("cvt.rna.tf32.f32 %0, %1;" : "=r"(u) : "f"(f));
    return u;
}
__device__ __forceinline__ float r32(float f) { return __uint_as_float(f2tf32(f)); }

__device__ __forceinline__ void mma_tf32(float4& c, const unsigned a[4],
                                         const unsigned b[2]) {
    asm volatile(
        "mma.sync.aligned.m16n8k8.row.col.f32.tf32.tf32.f32 "
        "{%0,%1,%2,%3}, {%4,%5,%6,%7}, {%8,%9}, {%0,%1,%2,%3};\n"
        : "+f"(c.x), "+f"(c.y), "+f"(c.z), "+f"(c.w)
        : "r"(a[0]), "r"(a[1]), "r"(a[2]), "r"(a[3]), "r"(b[0]), "r"(b[1]));
}

__device__ __forceinline__ unsigned sptr(const void* p) {
    return (unsigned)__cvta_generic_to_shared(p);
}
#define CP_ASYNC16(dst, src) \
    asm volatile("cp.async.cg.shared.global [%0], [%1], 16;" :: "r"(dst), "l"(src))

// ---------------------------------------------------------------------------
// Prepass: elementwise tf32 rounding (float4 vectorized)
// ---------------------------------------------------------------------------
__global__ void cvt_tf32_k(const float* __restrict__ in, float* __restrict__ out)
{
    int i = blockIdx.x * blockDim.x + threadIdx.x;
    float4 v = ((const float4*)in)[i];
    v.x = r32(v.x); v.y = r32(v.y); v.z = r32(v.z); v.w = r32(v.w);
    ((float4*)out)[i] = v;
}

// ---------------------------------------------------------------------------
// tf32 GEMM: C[M,N] = A[M,K] @ B[K,N], row-major, operands pre-rounded to tf32.
// 128x128 CTA, BK=32, 128 threads (4 warps, 2x2), warp tile 64x64.
// 3-deep cp.async ring, ONE __syncthreads per K-iteration, no cvt in loop.
// ---------------------------------------------------------------------------
constexpr int GA_ST = 36;    // A smem row stride (words)
constexpr int GB_ST = 136;   // B smem row stride (words)
constexpr int GBUF  = 128 * GA_ST + 32 * GB_ST;              // words per buffer
constexpr int GEMM_SMEM = 3 * GBUF * 4;                      // 107520 B

__global__ __launch_bounds__(128, 2) void gemm_tf32(
    const float* __restrict__ A, const float* __restrict__ B,
    float* __restrict__ C, int M, int N, int K)
{
    extern __shared__ float gsh[];

    const int tid  = threadIdx.x;
    const int warp = tid >> 5, lane = tid & 31;
    const int g  = lane >> 2;
    const int i4 = lane & 3;
    const int wm = (warp >> 1) * 64;
    const int wn = (warp & 1) * 64;
    const int brow = blockIdx.y * 128;
    const int bcol = blockIdx.x * 128;

    float4 acc[4][8];
    #pragma unroll
    for (int mt = 0; mt < 4; mt++)
        #pragma unroll
        for (int nt = 0; nt < 8; nt++)
            acc[mt][nt] = make_float4(0.f, 0.f, 0.f, 0.f);

    const int NIT = K >> 5;   // K/32

    auto stage = [&](int s, int buf) {
        float* a_dst = gsh + buf * GBUF;
        float* b_dst = a_dst + 128 * GA_ST;
        const int kt = s << 5;
        #pragma unroll
        for (int i = 0; i < 8; i++) {
            int id = tid + 128 * i;           // 0..1023
            int r = id >> 3, c4 = (id & 7) * 4;
            CP_ASYNC16(sptr(&a_dst[r * GA_ST + c4]),
                       &A[(size_t)(brow + r) * K + kt + c4]);
        }
        #pragma unroll
        for (int i = 0; i < 8; i++) {
            int id = tid + 128 * i;
            int k = id >> 5, n4 = (id & 31) * 4;
            CP_ASYNC16(sptr(&b_dst[k * GB_ST + n4]),
                       &B[(size_t)(kt + k) * N + bcol + n4]);
        }
        asm volatile("cp.async.commit_group;");
    };

    stage(0, 0);
    stage(1, 1);

    #pragma unroll 1
    for (int s = 0; s < NIT; s++) {
        const int b = s % 3;
        if (s < NIT - 1) { asm volatile("cp.async.wait_group 1;"); }
        else             { asm volatile("cp.async.wait_group 0;"); }
        __syncthreads();   // buffer b visible; all threads done with iter s-1

        if (s + 2 < NIT) stage(s + 2, (s + 2) % 3);

        const float* a_src = gsh + b * GBUF;
        const float* b_src = a_src + 128 * GA_ST;

        #pragma unroll
        for (int ks = 0; ks < 4; ks++) {
            unsigned af[4][4], bf[8][2];
            #pragma unroll
            for (int mt = 0; mt < 4; mt++) {
                const float* ap = &a_src[(wm + mt * 16 + g) * GA_ST + ks * 8 + i4];
                af[mt][0] = __float_as_uint(ap[0]);
                af[mt][1] = __float_as_uint(ap[8 * GA_ST]);
                af[mt][2] = __float_as_uint(ap[4]);
                af[mt][3] = __float_as_uint(ap[8 * GA_ST + 4]);
            }
            #pragma unroll
            for (int nt = 0; nt < 8; nt++) {
                const float* bp = &b_src[(ks * 8 + i4) * GB_ST + wn + nt * 8 + g];
                bf[nt][0] = __float_as_uint(bp[0]);
                bf[nt][1] = __float_as_uint(bp[4 * GB_ST]);
            }
            #pragma unroll
            for (int mt = 0; mt < 4; mt++)
                #pragma unroll
                for (int nt = 0; nt < 8; nt++)
                    mma_tf32(acc[mt][nt], af[mt], bf[nt]);
        }
    }

    // Epilogue
    #pragma unroll
    for (int mt = 0; mt < 4; mt++) {
        int row = brow + wm + mt * 16 + g;
        #pragma unroll
        for (int nt = 0; nt < 8; nt++) {
            int col = bcol + wn + nt * 8 + i4 * 2;
            *(float2*)&C[(size_t)row * N + col] =
                make_float2(acc[mt][nt].x, acc[mt][nt].y);
            *(float2*)&C[(size_t)(row + 8) * N + col] =
                make_float2(acc[mt][nt].z, acc[mt][nt].w);
        }
    }
}

// ---------------------------------------------------------------------------
// Flash attention, tf32 MMA, RoPE fused into Q/K loads.
// BM=128 (4 warps x m32), BN=64, HD=64, causal. 128 threads.
// Q fragments hoisted to registers (loaded once, reused every kt iteration).
// ---------------------------------------------------------------------------
constexpr int AQ_ST = 136;  // Qs [d][m]
constexpr int AK_ST = 72;   // Ks [key][d]
constexpr int AV_ST = 72;   // Vs [key][d]
constexpr int AP_ST = 68;   // Ps [m][key]
constexpr int ATTN_SMEM =
    (64 * AQ_ST + 64 * AK_ST + 64 * AV_ST + 128 * AP_ST) * 4;  // 106496 B

__global__ __launch_bounds__(128, 2) void attn_tf32(
    const float* __restrict__ qkv, const float* __restrict__ rope,
    float* __restrict__ out)
{
    extern __shared__ unsigned ash[];
    unsigned* Qs = ash;                  // [64 d][AQ_ST m] (transposed, scaled, roped)
    unsigned* Ks = Qs + 64 * AQ_ST;      // [64 key][AK_ST d] (roped)
    unsigned* Vs = Ks + 64 * AK_ST;      // [64 key][AV_ST d]
    unsigned* Ps = Vs + 64 * AV_ST;      // [128 m][AP_ST key] (warp-private rows)

    const int tid  = threadIdx.x;
    const int warp = tid >> 5, lane = tid & 31;
    const int g  = lane >> 2;
    const int i4 = lane & 3;
    const int qt = gridDim.x - 1 - blockIdx.x;   // big tiles first
    const int h  = blockIdx.y;
    const int b  = blockIdx.z;

    // ---- Load Q tile (128 rows x 64 dims), RoPE + scale, transposed ----
    #pragma unroll
    for (int i = 0; i < 16; i++) {
        int id  = tid + 128 * i;          // 0..2047
        int row = id & 127;
        int d4  = (id >> 7) * 4;
        int t   = qt * 128 + row;
        float4 v = *(const float4*)
            &qkv[((size_t)(b * kNT + t)) * 3072 + h * 64 + d4];
        int p0 = d4 >> 1;
        float c0 = rope[(t * 32 + p0) * 2],     s0 = rope[(t * 32 + p0) * 2 + 1];
        float c1 = rope[(t * 32 + p0 + 1) * 2], s1 = rope[(t * 32 + p0 + 1) * 2 + 1];
        float q0 = v.x * c0 - v.y * s0, q1 = v.y * c0 + v.x * s0;
        float q2 = v.z * c1 - v.w * s1, q3 = v.w * c1 + v.z * s1;
        Qs[(d4 + 0) * AQ_ST + row] = f2tf32(q0 * 0.125f);
        Qs[(d4 + 1) * AQ_ST + row] = f2tf32(q1 * 0.125f);
        Qs[(d4 + 2) * AQ_ST + row] = f2tf32(q2 * 0.125f);
        Qs[(d4 + 3) * AQ_ST + row] = f2tf32(q3 * 0.125f);
    }
    __syncthreads();

    // ---- Hoist Q A-fragments into registers (invariant across kt) ----
    unsigned qf[2][8][4];
    #pragma unroll
    for (int mt = 0; mt < 2; mt++) {
        int r = warp * 32 + mt * 16 + g;
        #pragma unroll
        for (int ks = 0; ks < 8; ks++) {
            qf[mt][ks][0] = Qs[(ks * 8 + i4) * AQ_ST + r];
            qf[mt][ks][1] = Qs[(ks * 8 + i4) * AQ_ST + r + 8];
            qf[mt][ks][2] = Qs[(ks * 8 + i4 + 4) * AQ_ST + r];
            qf[mt][ks][3] = Qs[(ks * 8 + i4 + 4) * AQ_ST + r + 8];
        }
    }

    float m[2][2], l[2][2];
    #pragma unroll
    for (int mt = 0; mt < 2; mt++) {
        m[mt][0] = m[mt][1] = -1e30f;
        l[mt][0] = l[mt][1] = 0.f;
    }
    float4 o[2][8];
    #pragma unroll
    for (int mt = 0; mt < 2; mt++)
        #pragma unroll
        for (int nt = 0; nt < 8; nt++)
            o[mt][nt] = make_float4(0.f, 0.f, 0.f, 0.f);

    const int nkt = 2 * qt + 2;
    for (int kt = 0; kt < nkt; kt++) {
        __syncthreads();   // previous PV reads of Ks/Vs done
        // ---- Load K (roped) and V tiles: 64 rows x 64 dims each ----
        #pragma unroll
        for (int i = 0; i < 8; i++) {
            int id  = tid + 128 * i;      // 0..1023
            int row = id >> 4;
            int d4  = (id & 15) * 4;
            int t   = kt * 64 + row;
            size_t gb = ((size_t)(b * kNT + t)) * 3072 + h * 64 + d4;
            float4 kv = *(const float4*)&qkv[gb + 1024];
            int p0 = d4 >> 1;
            float c0 = rope[(t * 32 + p0) * 2],     s0 = rope[(t * 32 + p0) * 2 + 1];
            float c1 = rope[(t * 32 + p0 + 1) * 2], s1 = rope[(t * 32 + p0 + 1) * 2 + 1];
            uint4 kk;
            kk.x = f2tf32(kv.x * c0 - kv.y * s0);
            kk.y = f2tf32(kv.y * c0 + kv.x * s0);
            kk.z = f2tf32(kv.z * c1 - kv.w * s1);
            kk.w = f2tf32(kv.w * c1 + kv.z * s1);
            *(uint4*)&Ks[row * AK_ST + d4] = kk;
            float4 vv = *(const float4*)&qkv[gb + 2048];
            uint4 vu;
            vu.x = f2tf32(vv.x); vu.y = f2tf32(vv.y);
            vu.z = f2tf32(vv.z); vu.w = f2tf32(vv.w);
            *(uint4*)&Vs[row * AV_ST + d4] = vu;
        }
        __syncthreads();

        // Warps whose rows are entirely left of this key tile skip compute.
        if (kt * 64 <= qt * 128 + warp * 32 + 31) {
            // ---- S = Q @ K^T ----
            float4 s[2][8];
            #pragma unroll
            for (int mt = 0; mt < 2; mt++)
                #pragma unroll
                for (int nt = 0; nt < 8; nt++)
                    s[mt][nt] = make_float4(0.f, 0.f, 0.f, 0.f);

            #pragma unroll
            for (int ks = 0; ks < 8; ks++) {
                #pragma unroll
                for (int nt = 0; nt < 8; nt++) {
                    unsigned bf[2];
                    int key = nt * 8 + g;
                    bf[0] = Ks[key * AK_ST + ks * 8 + i4];
                    bf[1] = Ks[key * AK_ST + ks * 8 + i4 + 4];
                    mma_tf32(s[0][nt], qf[0][ks], bf);
                    mma_tf32(s[1][nt], qf[1][ks], bf);
                }
            }

            // ---- Causal mask (only tiles crossing the diagonal) ----
            if (kt >= 2 * qt) {
                #pragma unroll
                for (int mt = 0; mt < 2; mt++) {
                    int r0 = qt * 128 + warp * 32 + mt * 16 + g;
                    #pragma unroll
                    for (int nt = 0; nt < 8; nt++) {
                        int c0 = kt * 64 + nt * 8 + i4 * 2;
                        if (c0     > r0)     s[mt][nt].x = -1e30f;
                        if (c0 + 1 > r0)     s[mt][nt].y = -1e30f;
                        if (c0     > r0 + 8) s[mt][nt].z = -1e30f;
                        if (c0 + 1 > r0 + 8) s[mt][nt].w = -1e30f;
                    }
                }
            }

            // ---- Online softmax + P store (warp-private rows of Ps) ----
            #pragma unroll
            for (int mt = 0; mt < 2; mt++) {
                float mx0 = -1e30f, mx1 = -1e30f;
                #pragma unroll
                for (int nt = 0; nt < 8; nt++) {
                    mx0 = fmaxf(mx0, fmaxf(s[mt][nt].x, s[mt][nt].y));
                    mx1 = fmaxf(mx1, fmaxf(s[mt][nt].z, s[mt][nt].w));
                }
                mx0 = fmaxf(mx0, __shfl_xor_sync(0xffffffffu, mx0, 1));
                mx0 = fmaxf(mx0, __shfl_xor_sync(0xffffffffu, mx0, 2));
                mx1 = fmaxf(mx1, __shfl_xor_sync(0xffffffffu, mx1, 1));
                mx1 = fmaxf(mx1, __shfl_xor_sync(0xffffffffu, mx1, 2));
                float nm0 = fmaxf(m[mt][0], mx0), nm1 = fmaxf(m[mt][1], mx1);
                float f0 = __expf(m[mt][0] - nm0), f1 = __expf(m[mt][1] - nm1);
                float sum0 = 0.f, sum1 = 0.f;
                int r = warp * 32 + mt * 16 + g;
                #pragma unroll
                for (int nt = 0; nt < 8; nt++) {
                    float px = __expf(s[mt][nt].x - nm0);
                    float py = __expf(s[mt][nt].y - nm0);
                    float pz = __expf(s[mt][nt].z - nm1);
                    float pw = __expf(s[mt][nt].w - nm1);
                    sum0 += px + py;
                    sum1 += pz + pw;
                    uint2 lo = make_uint2(f2tf32(px), f2tf32(py));
                    uint2 hi = make_uint2(f2tf32(pz), f2tf32(pw));
                    *(uint2*)&Ps[r * AP_ST + nt * 8 + i4 * 2] = lo;
                    *(uint2*)&Ps[(r + 8) * AP_ST + nt * 8 + i4 * 2] = hi;
                }
                sum0 += __shfl_xor_sync(0xffffffffu, sum0, 1);
                sum0 += __shfl_xor_sync(0xffffffffu, sum0, 2);
                sum1 += __shfl_xor_sync(0xffffffffu, sum1, 1);
                sum1 += __shfl_xor_sync(0xffffffffu, sum1, 2);
                l[mt][0] = l[mt][0] * f0 + sum0;  m[mt][0] = nm0;
                l[mt][1] = l[mt][1] * f1 + sum1;  m[mt][1] = nm1;
                #pragma unroll
                for (int nt = 0; nt < 8; nt++) {
                    o[mt][nt].x *= f0; o[mt][nt].y *= f0;
                    o[mt][nt].z *= f1; o[mt][nt].w *= f1;
                }
            }
            __syncwarp();   // Ps rows are warp-private

            // ---- O += P @ V ----
            #pragma unroll
            for (int ks = 0; ks < 8; ks++) {
                unsigned af[2][4];
                #pragma unroll
                for (int mt = 0; mt < 2; mt++) {
                    int r = warp * 32 + mt * 16 + g;
                    af[mt][0] = Ps[r * AP_ST + ks * 8 + i4];
                    af[mt][1] = Ps[(r + 8) * AP_ST + ks * 8 + i4];
                    af[mt][2] = Ps[r * AP_ST + ks * 8 + i4 + 4];
                    af[mt][3] = Ps[(r + 8) * AP_ST + ks * 8 + i4 + 4];
                }
                #pragma unroll
                for (int nt = 0; nt < 8; nt++) {
                    unsigned bf[2];
                    bf[0] = Vs[(ks * 8 + i4) * AV_ST + nt * 8 + g];
                    bf[1] = Vs[(ks * 8 + i4 + 4) * AV_ST + nt * 8 + g];
                    mma_tf32(o[0][nt], af[0], bf);
                    mma_tf32(o[1][nt], af[1], bf);
                }
            }
        }
    }

    // ---- Epilogue: tf32-rounded output (pre-rounded A for the proj GEMM) ----
    #pragma unroll
    for (int mt = 0; mt < 2; mt++) {
        float inv0 = 1.0f / l[mt][0], inv1 = 1.0f / l[mt][1];
        int r = qt * 128 + warp * 32 + mt * 16 + g;
        #pragma unroll
        for (int nt = 0; nt < 8; nt++) {
            int col = h * 64 + nt * 8 + i4 * 2;
            *(float2*)&out[((size_t)(b * kNT + r)) * 1024 + col] =
                make_float2(r32(o[mt][nt].x * inv0), r32(o[mt][nt].y * inv0));
            *(float2*)&out[((size_t)(b * kNT + r + 8)) * 1024 + col] =
                make_float2(r32(o[mt][nt].z * inv1), r32(o[mt][nt].w * inv1));
        }
    }
}

// ---------------------------------------------------------------------------
// Launch
// ---------------------------------------------------------------------------
extern "C" void kernel_launch(void* const* d_in, const int* in_sizes, int n_in,
                              void* d_out, int out_size)
{
    const float* x      = (const float*)d_in[0];
    const float* rope   = (const float*)d_in[1];
    const float* W_attn = (const float*)d_in[2];
    const float* W_proj = (const float*)d_in[3];
    float* out = (float*)d_out;

    float* qkv;  cudaGetSymbolAddress((void**)&qkv,  g_qkv);
    float* attn; cudaGetSymbolAddress((void**)&attn, g_attn);
    float* xc;   cudaGetSymbolAddress((void**)&xc,   g_xc);
    float* wac;  cudaGetSymbolAddress((void**)&wac,  g_wac);
    float* wpc;  cudaGetSymbolAddress((void**)&wpc,  g_wpc);

    cudaFuncSetAttribute(gemm_tf32,
                         cudaFuncAttributeMaxDynamicSharedMemorySize, GEMM_SMEM);
    cudaFuncSetAttribute(attn_tf32,
                         cudaFuncAttributeMaxDynamicSharedMemorySize, ATTN_SMEM);

    // Prepass: round operands to tf32 once (removes cvt from GEMM hot loops)
    cvt_tf32_k<<<(kNM * kND / 4) / 256, 256>>>(x, xc);
    cvt_tf32_k<<<(kND * 3 * kND / 4) / 256, 256>>>(W_attn, wac);
    cvt_tf32_k<<<(kND * kND / 4) / 256, 256>>>(W_proj, wpc);

    // 1. QKV = x @ W_attn : (4096,1024) @ (1024,3072)
    gemm_tf32<<<dim3(3 * kND / 128, kNM / 128), 128, GEMM_SMEM>>>(
        xc, wac, qkv, kNM, 3 * kND, kND);

    // 2. Causal flash attention (RoPE fused into Q/K loads)
    attn_tf32<<<dim3(kNT / 128, kNH, kNB), 128, ATTN_SMEM>>>(qkv, rope, attn);

    // 3. out = attn @ W_proj : (4096,1024) @ (1024,1024)
    gemm_tf32<<<dim3(kND / 128, kNM / 128), 128, GEMM_SMEM>>>(
        attn, wpc, out, kNM, kND, kND);
}

// round 7
// speedup vs baseline: 1.6335x; 1.6335x over previous
#include <cuda_runtime.h>
#include <cuda_fp16.h>
#include <cstdint>

// Problem constants
constexpr int kNB = 2;
constexpr int kNT = 2048;
constexpr int kND = 1024;
constexpr int kNH = 16;
constexpr int kNM = kNB * kNT;   // 4096 rows

// Scratch (allocation-free rule: device globals), all fp16
__device__ __half g_qkv[(size_t)kNM * 3 * kND];   // (4096, 3072)
__device__ __half g_attn[(size_t)kNM * kND];      // (4096, 1024)
__device__ __half g_xh[(size_t)kNM * kND];        // x -> fp16 [m][k]
__device__ __half g_wat[(size_t)3 * kND * kND];   // W_attn^T fp16 [n][k]
__device__ __half g_wpt[(size_t)kND * kND];       // W_proj^T fp16 [n][k]

// ---------------------------------------------------------------------------
// Helpers
// ---------------------------------------------------------------------------
__device__ __forceinline__ uint32_t packh2(float a, float b) {
    __half2 h = __floats2half2_rn(a, b);
    return *(uint32_t*)&h;
}

__device__ __forceinline__ void mma_f16(float4& c, const uint32_t a[4],
                                        const uint32_t b[2]) {
    asm volatile(
        "mma.sync.aligned.m16n8k16.row.col.f32.f16.f16.f32 "
        "{%0,%1,%2,%3}, {%4,%5,%6,%7}, {%8,%9}, {%0,%1,%2,%3};\n"
        : "+f"(c.x), "+f"(c.y), "+f"(c.z), "+f"(c.w)
        : "r"(a[0]), "r"(a[1]), "r"(a[2]), "r"(a[3]), "r"(b[0]), "r"(b[1]));
}

__device__ __forceinline__ void ldsm_x2_trans(uint32_t& r0, uint32_t& r1,
                                              uint32_t saddr) {
    asm volatile("ldmatrix.sync.aligned.m8n8.x2.trans.shared.b16 {%0,%1}, [%2];"
                 : "=r"(r0), "=r"(r1) : "r"(saddr));
}

__device__ __forceinline__ unsigned sptr(const void* p) {
    return (unsigned)__cvta_generic_to_shared(p);
}
#define CP_ASYNC16(dst, src) \
    asm volatile("cp.async.cg.shared.global [%0], [%1], 16;" :: "r"(dst), "l"(src))

// ---------------------------------------------------------------------------
// Prepass: fp32 -> fp16 conversion / transposed conversion
// ---------------------------------------------------------------------------
__global__ void cvt_h(const float* __restrict__ in, __half* __restrict__ out)
{
    int i = blockIdx.x * blockDim.x + threadIdx.x;
    float4 v = ((const float4*)in)[i];
    uint2 o;
    o.x = packh2(v.x, v.y);
    o.y = packh2(v.z, v.w);
    ((uint2*)out)[i] = o;
}

__global__ void transpose_h(const float* __restrict__ in, __half* __restrict__ out,
                            int R, int C)
{
    __shared__ float t[32][33];
    int c0 = blockIdx.x * 32, r0 = blockIdx.y * 32;
    for (int i = threadIdx.y; i < 32; i += 8)
        t[i][threadIdx.x] = in[(size_t)(r0 + i) * C + c0 + threadIdx.x];
    __syncthreads();
    for (int i = threadIdx.y; i < 32; i += 8)
        out[(size_t)(c0 + i) * R + r0 + threadIdx.x] = __float2half(t[threadIdx.x][i]);
}

// ---------------------------------------------------------------------------
// fp16 GEMM: C[M,N] = A[M,K] @ Bt[N,K]^T, A/Bt fp16 k-major.
// 128x128 CTA, BK=32, 128 threads (4 warps 2x2), warp tile 64x64, m16n8k16.
// 3-deep cp.async ring, one __syncthreads per K-iter.
// ---------------------------------------------------------------------------
constexpr int RST  = 20;                 // uints per smem row (32 fp16 + pad)
constexpr int GBUF = 2 * 128 * RST;      // uints per buffer (A+B)
constexpr int GEMM_SMEM = 3 * GBUF * 4;  // 61440 B

template <bool HOUT>
__global__ __launch_bounds__(128, 2) void gemm_f16(
    const __half* __restrict__ A, const __half* __restrict__ Bt,
    void* __restrict__ Cv, int M, int N, int K)
{
    extern __shared__ uint32_t gsh[];

    const int tid  = threadIdx.x;
    const int warp = tid >> 5, lane = tid & 31;
    const int g  = lane >> 2;
    const int i4 = lane & 3;
    const int wm = (warp >> 1) * 64;
    const int wn = (warp & 1) * 64;
    const int brow = blockIdx.y * 128;
    const int bcol = blockIdx.x * 128;
    const uint32_t sbase = sptr(gsh);

    float4 acc[4][8];
    #pragma unroll
    for (int mt = 0; mt < 4; mt++)
        #pragma unroll
        for (int nt = 0; nt < 8; nt++)
            acc[mt][nt] = make_float4(0.f, 0.f, 0.f, 0.f);

    const int NIT = K >> 5;

    auto stage = [&](int s, int buf) {
        uint32_t ab = sbase + buf * GBUF * 4;
        uint32_t bb = ab + 128 * RST * 4;
        const __half* Ag = A + (size_t)brow * K + (s << 5);
        const __half* Bg = Bt + (size_t)bcol * K + (s << 5);
        #pragma unroll
        for (int i = 0; i < 4; i++) {
            int id = tid + 128 * i;          // 0..511
            int r = id >> 2, ch = id & 3;    // 128 rows x 4 16B-chunks
            CP_ASYNC16(ab + r * 80 + ch * 16, Ag + (size_t)r * K + ch * 8);
            CP_ASYNC16(bb + r * 80 + ch * 16, Bg + (size_t)r * K + ch * 8);
        }
        asm volatile("cp.async.commit_group;");
    };

    stage(0, 0);
    stage(1, 1);

    #pragma unroll 1
    for (int s = 0; s < NIT; s++) {
        const int b = s % 3;
        if (s < NIT - 1) { asm volatile("cp.async.wait_group 1;"); }
        else             { asm volatile("cp.async.wait_group 0;"); }
        __syncthreads();

        if (s + 2 < NIT) stage(s + 2, (s + 2) % 3);

        const uint32_t* a_src = gsh + b * GBUF;
        const uint32_t* b_src = a_src + 128 * RST;

        #pragma unroll
        for (int kk = 0; kk < 2; kk++) {
            uint32_t af[4][4], bf[8][2];
            #pragma unroll
            for (int mt = 0; mt < 4; mt++) {
                int row = wm + mt * 16 + g;
                af[mt][0] = a_src[row * RST + kk * 8 + i4];
                af[mt][1] = a_src[(row + 8) * RST + kk * 8 + i4];
                af[mt][2] = a_src[row * RST + kk * 8 + i4 + 4];
                af[mt][3] = a_src[(row + 8) * RST + kk * 8 + i4 + 4];
            }
            #pragma unroll
            for (int nt = 0; nt < 8; nt++) {
                int cc = wn + nt * 8 + g;
                bf[nt][0] = b_src[cc * RST + kk * 8 + i4];
                bf[nt][1] = b_src[cc * RST + kk * 8 + i4 + 4];
            }
            #pragma unroll
            for (int mt = 0; mt < 4; mt++)
                #pragma unroll
                for (int nt = 0; nt < 8; nt++)
                    mma_f16(acc[mt][nt], af[mt], bf[nt]);
        }
    }

    // Epilogue
    #pragma unroll
    for (int mt = 0; mt < 4; mt++) {
        int row = brow + wm + mt * 16 + g;
        #pragma unroll
        for (int nt = 0; nt < 8; nt++) {
            int col = bcol + wn + nt * 8 + i4 * 2;
            if (HOUT) {
                __half* C = (__half*)Cv;
                *(uint32_t*)&C[(size_t)row * N + col] =
                    packh2(acc[mt][nt].x, acc[mt][nt].y);
                *(uint32_t*)&C[(size_t)(row + 8) * N + col] =
                    packh2(acc[mt][nt].z, acc[mt][nt].w);
            } else {
                float* C = (float*)Cv;
                *(float2*)&C[(size_t)row * N + col] =
                    make_float2(acc[mt][nt].x, acc[mt][nt].y);
                *(float2*)&C[(size_t)(row + 8) * N + col] =
                    make_float2(acc[mt][nt].z, acc[mt][nt].w);
            }
        }
    }
}

// ---------------------------------------------------------------------------
// Flash attention, fp16 MMA (m16n8k16), RoPE fused. BM=128 (4 warps x m32),
// BN=64, HD=64, causal, 128 threads. qkv fp16 in, attn fp16 out.
// ---------------------------------------------------------------------------
constexpr int QST = 36;   // uints per row (32 data + 4 pad)
constexpr int KST = 36;
constexpr int VST = 36;
constexpr int PST = 36;
constexpr int ATTN_SMEM = (128 * QST + 64 * KST + 64 * VST + 128 * PST) * 4; // 55296

__global__ __launch_bounds__(128, 2) void attn_f16(
    const __half* __restrict__ qkv, const float* __restrict__ rope,
    __half* __restrict__ out)
{
    extern __shared__ uint32_t ash[];
    uint32_t* Qs = ash;                  // [128 m][QST] fp16 pairs (roped, scaled)
    uint32_t* Ks = Qs + 128 * QST;       // [64 key][KST] (roped)
    uint32_t* Vs = Ks + 64 * KST;        // [64 key][VST] natural
    uint32_t* Ps = Vs + 64 * VST;        // [128 m][PST] P fp16

    const int tid  = threadIdx.x;
    const int warp = tid >> 5, lane = tid & 31;
    const int g  = lane >> 2;
    const int i4 = lane & 3;
    const int qt = gridDim.x - 1 - blockIdx.x;   // big tiles first
    const int h  = blockIdx.y;
    const int b  = blockIdx.z;
    const uint32_t vbase = sptr(Vs);

    // ---- Load Q tile (128 rows x 64 dims), RoPE + scale ----
    #pragma unroll
    for (int i = 0; i < 16; i++) {
        int id  = tid + 128 * i;          // 0..2047
        int row = id & 127;
        int d4  = (id >> 7) * 4;
        int t   = qt * 128 + row;
        uint2 raw = *(const uint2*)
            &qkv[((size_t)(b * kNT + t)) * 3072 + h * 64 + d4];
        __half2 p01 = *(__half2*)&raw.x, p23 = *(__half2*)&raw.y;
        float vx = __low2float(p01), vy = __high2float(p01);
        float vz = __low2float(p23), vw = __high2float(p23);
        int p0 = d4 >> 1;
        float c0 = rope[(t * 32 + p0) * 2],     s0 = rope[(t * 32 + p0) * 2 + 1];
        float c1 = rope[(t * 32 + p0 + 1) * 2], s1 = rope[(t * 32 + p0 + 1) * 2 + 1];
        float q0 = (vx * c0 - vy * s0) * 0.125f, q1 = (vy * c0 + vx * s0) * 0.125f;
        float q2 = (vz * c1 - vw * s1) * 0.125f, q3 = (vw * c1 + vz * s1) * 0.125f;
        uint2 st = make_uint2(packh2(q0, q1), packh2(q2, q3));
        *(uint2*)&Qs[row * QST + (d4 >> 1)] = st;
    }
    __syncthreads();

    // ---- Hoist Q A-fragments (invariant across kt) ----
    uint32_t qf[2][4][4];
    #pragma unroll
    for (int mt = 0; mt < 2; mt++) {
        int r = warp * 32 + mt * 16 + g;
        #pragma unroll
        for (int kk = 0; kk < 4; kk++) {
            qf[mt][kk][0] = Qs[r * QST + kk * 8 + i4];
            qf[mt][kk][1] = Qs[(r + 8) * QST + kk * 8 + i4];
            qf[mt][kk][2] = Qs[r * QST + kk * 8 + i4 + 4];
            qf[mt][kk][3] = Qs[(r + 8) * QST + kk * 8 + i4 + 4];
        }
    }

    float m[2][2], l[2][2];
    #pragma unroll
    for (int mt = 0; mt < 2; mt++) {
        m[mt][0] = m[mt][1] = -1e30f;
        l[mt][0] = l[mt][1] = 0.f;
    }
    float4 o[2][8];
    #pragma unroll
    for (int mt = 0; mt < 2; mt++)
        #pragma unroll
        for (int nt = 0; nt < 8; nt++)
            o[mt][nt] = make_float4(0.f, 0.f, 0.f, 0.f);

    const int nkt = 2 * qt + 2;
    for (int kt = 0; kt < nkt; kt++) {
        __syncthreads();   // previous PV reads of Ks/Vs done
        // ---- Load K (roped) and V tiles ----
        #pragma unroll
        for (int i = 0; i < 8; i++) {
            int id  = tid + 128 * i;      // 0..1023
            int row = id >> 4;
            int d4  = (id & 15) * 4;
            int t   = kt * 64 + row;
            size_t gb = ((size_t)(b * kNT + t)) * 3072 + h * 64 + d4;
            uint2 kraw = *(const uint2*)&qkv[gb + 1024];
            __half2 k01 = *(__half2*)&kraw.x, k23 = *(__half2*)&kraw.y;
            float kx = __low2float(k01), ky = __high2float(k01);
            float kz = __low2float(k23), kw = __high2float(k23);
            int p0 = d4 >> 1;
            float c0 = rope[(t * 32 + p0) * 2],     s0 = rope[(t * 32 + p0) * 2 + 1];
            float c1 = rope[(t * 32 + p0 + 1) * 2], s1 = rope[(t * 32 + p0 + 1) * 2 + 1];
            uint2 kst = make_uint2(packh2(kx * c0 - ky * s0, ky * c0 + kx * s0),
                                   packh2(kz * c1 - kw * s1, kw * c1 + kz * s1));
            *(uint2*)&Ks[row * KST + (d4 >> 1)] = kst;
            uint2 vraw = *(const uint2*)&qkv[gb + 2048];
            *(uint2*)&Vs[row * VST + (d4 >> 1)] = vraw;
        }
        __syncthreads();

        // Warps whose rows are entirely left of this key tile skip compute.
        if (kt * 64 <= qt * 128 + warp * 32 + 31) {
            // ---- S = Q @ K^T ----
            float4 s[2][8];
            #pragma unroll
            for (int mt = 0; mt < 2; mt++)
                #pragma unroll
                for (int nt = 0; nt < 8; nt++)
                    s[mt][nt] = make_float4(0.f, 0.f, 0.f, 0.f);

            #pragma unroll
            for (int kk = 0; kk < 4; kk++) {
                #pragma unroll
                for (int nt = 0; nt < 8; nt++) {
                    uint32_t bf[2];
                    int key = nt * 8 + g;
                    bf[0] = Ks[key * KST + kk * 8 + i4];
                    bf[1] = Ks[key * KST + kk * 8 + i4 + 4];
                    mma_f16(s[0][nt], qf[0][kk], bf);
                    mma_f16(s[1][nt], qf[1][kk], bf);
                }
            }

            // ---- Causal mask ----
            if (kt >= 2 * qt) {
                #pragma unroll
                for (int mt = 0; mt < 2; mt++) {
                    int r0 = qt * 128 + warp * 32 + mt * 16 + g;
                    #pragma unroll
                    for (int nt = 0; nt < 8; nt++) {
                        int c0 = kt * 64 + nt * 8 + i4 * 2;
                        if (c0     > r0)     s[mt][nt].x = -1e30f;
                        if (c0 + 1 > r0)     s[mt][nt].y = -1e30f;
                        if (c0     > r0 + 8) s[mt][nt].z = -1e30f;
                        if (c0 + 1 > r0 + 8) s[mt][nt].w = -1e30f;
                    }
                }
            }

            // ---- Online softmax + P store (fp16, warp-private rows) ----
            #pragma unroll
            for (int mt = 0; mt < 2; mt++) {
                float mx0 = -1e30f, mx1 = -1e30f;
                #pragma unroll
                for (int nt = 0; nt < 8; nt++) {
                    mx0 = fmaxf(mx0, fmaxf(s[mt][nt].x, s[mt][nt].y));
                    mx1 = fmaxf(mx1, fmaxf(s[mt][nt].z, s[mt][nt].w));
                }
                mx0 = fmaxf(mx0, __shfl_xor_sync(0xffffffffu, mx0, 1));
                mx0 = fmaxf(mx0, __shfl_xor_sync(0xffffffffu, mx0, 2));
                mx1 = fmaxf(mx1, __shfl_xor_sync(0xffffffffu, mx1, 1));
                mx1 = fmaxf(mx1, __shfl_xor_sync(0xffffffffu, mx1, 2));
                float nm0 = fmaxf(m[mt][0], mx0), nm1 = fmaxf(m[mt][1], mx1);
                float f0 = __expf(m[mt][0] - nm0), f1 = __expf(m[mt][1] - nm1);
                float sum0 = 0.f, sum1 = 0.f;
                int r = warp * 32 + mt * 16 + g;
                #pragma unroll
                for (int nt = 0; nt < 8; nt++) {
                    float px = __expf(s[mt][nt].x - nm0);
                    float py = __expf(s[mt][nt].y - nm0);
                    float pz = __expf(s[mt][nt].z - nm1);
                    float pw = __expf(s[mt][nt].w - nm1);
                    sum0 += px + py;
                    sum1 += pz + pw;
                    Ps[r * PST + nt * 4 + i4]       = packh2(px, py);
                    Ps[(r + 8) * PST + nt * 4 + i4] = packh2(pz, pw);
                }
                sum0 += __shfl_xor_sync(0xffffffffu, sum0, 1);
                sum0 += __shfl_xor_sync(0xffffffffu, sum0, 2);
                sum1 += __shfl_xor_sync(0xffffffffu, sum1, 1);
                sum1 += __shfl_xor_sync(0xffffffffu, sum1, 2);
                l[mt][0] = l[mt][0] * f0 + sum0;  m[mt][0] = nm0;
                l[mt][1] = l[mt][1] * f1 + sum1;  m[mt][1] = nm1;
                #pragma unroll
                for (int nt = 0; nt < 8; nt++) {
                    o[mt][nt].x *= f0; o[mt][nt].y *= f0;
                    o[mt][nt].z *= f1; o[mt][nt].w *= f1;
                }
            }
            __syncwarp();   // Ps rows are warp-private

            // ---- O += P @ V (V fragments via ldmatrix.trans) ----
            #pragma unroll
            for (int kk = 0; kk < 4; kk++) {
                uint32_t af[2][4];
                #pragma unroll
                for (int mt = 0; mt < 2; mt++) {
                    int r = warp * 32 + mt * 16 + g;
                    af[mt][0] = Ps[r * PST + kk * 8 + i4];
                    af[mt][1] = Ps[(r + 8) * PST + kk * 8 + i4];
                    af[mt][2] = Ps[r * PST + kk * 8 + i4 + 4];
                    af[mt][3] = Ps[(r + 8) * PST + kk * 8 + i4 + 4];
                }
                #pragma unroll
                for (int nt = 0; nt < 8; nt++) {
                    uint32_t bf[2];
                    uint32_t va = vbase +
                        ((kk * 16 + (lane & 15)) * VST + nt * 4) * 4;
                    ldsm_x2_trans(bf[0], bf[1], va);
                    mma_f16(o[0][nt], af[0], bf);
                    mma_f16(o[1][nt], af[1], bf);
                }
            }
        }
    }

    // ---- Epilogue: fp16 output ----
    #pragma unroll
    for (int mt = 0; mt < 2; mt++) {
        float inv0 = 1.0f / l[mt][0], inv1 = 1.0f / l[mt][1];
        int r = qt * 128 + warp * 32 + mt * 16 + g;
        #pragma unroll
        for (int nt = 0; nt < 8; nt++) {
            int col = h * 64 + nt * 8 + i4 * 2;
            *(uint32_t*)&out[((size_t)(b * kNT + r)) * 1024 + col] =
                packh2(o[mt][nt].x * inv0, o[mt][nt].y * inv0);
            *(uint32_t*)&out[((size_t)(b * kNT + r + 8)) * 1024 + col] =
                packh2(o[mt][nt].z * inv1, o[mt][nt].w * inv1);
        }
    }
}

// ---------------------------------------------------------------------------
// Launch
// ---------------------------------------------------------------------------
extern "C" void kernel_launch(void* const* d_in, const int* in_sizes, int n_in,
                              void* d_out, int out_size)
{
    const float* x      = (const float*)d_in[0];
    const float* rope   = (const float*)d_in[1];
    const float* W_attn = (const float*)d_in[2];
    const float* W_proj = (const float*)d_in[3];
    float* out = (float*)d_out;

    __half* qkv;  cudaGetSymbolAddress((void**)&qkv,  g_qkv);
    __half* attn; cudaGetSymbolAddress((void**)&attn, g_attn);
    __half* xh;   cudaGetSymbolAddress((void**)&xh,   g_xh);
    __half* wat;  cudaGetSymbolAddress((void**)&wat,  g_wat);
    __half* wpt;  cudaGetSymbolAddress((void**)&wpt,  g_wpt);

    cudaFuncSetAttribute(gemm_f16<true>,
                         cudaFuncAttributeMaxDynamicSharedMemorySize, GEMM_SMEM);
    cudaFuncSetAttribute(gemm_f16<false>,
                         cudaFuncAttributeMaxDynamicSharedMemorySize, GEMM_SMEM);
    cudaFuncSetAttribute(attn_f16,
                         cudaFuncAttributeMaxDynamicSharedMemorySize, ATTN_SMEM);

    // Prepass: x -> fp16; W_attn/W_proj -> fp16 transposed [n][k]
    cvt_h<<<(kNM * kND / 4) / 256, 256>>>(x, xh);
    transpose_h<<<dim3(3 * kND / 32, kND / 32), dim3(32, 8)>>>(W_attn, wat,
                                                               kND, 3 * kND);
    transpose_h<<<dim3(kND / 32, kND / 32), dim3(32, 8)>>>(W_proj, wpt,
                                                           kND, kND);

    // 1. QKV = x @ W_attn : fp16 out
    gemm_f16<true><<<dim3(3 * kND / 128, kNM / 128), 128, GEMM_SMEM>>>(
        xh, wat, qkv, kNM, 3 * kND, kND);

    // 2. Causal flash attention (RoPE fused), fp16 in/out
    attn_f16<<<dim3(kNT / 128, kNH, kNB), 128, ATTN_SMEM>>>(qkv, rope, attn);

    // 3. out = attn @ W_proj : fp32 out
    gemm_f16<false><<<dim3(kND / 128, kNM / 128), 128, GEMM_SMEM>>>(
        attn, wpt, out, kNM, kND, kND);
}